// round 13
// baseline (speedup 1.0000x reference)
#include <cuda_runtime.h>
#include <stdint.h>

// Problem constants
#define NB   8
#define HW   128
#define OC   16
#define NF   27
#define NROWS_TOT 1024        // NB*HW global output rows
#define NSPLIT    148         // row-range splits (one per SM)
#define GRID_CONV (2*NSPLIT)  // x2 channel halves

// Device scratch: two half-tables, 16B rows (8 channels each).
__device__ __align__(16) short g_prodA[NF*256*8];   // [f][ip][o:0-7]   108KB
__device__ __align__(16) short g_prodB[NF*256*8];   // [f][ip][o:8-15]  108KB

// ---------------------------------------------------------------------------
// Table builder: one thread per (f, ip, o).
// ---------------------------------------------------------------------------
__global__ void prep_table(const float* __restrict__ w,
                           const float* __restrict__ swp,
                           const int*   __restrict__ lut)
{
    int idx = blockIdx.x * blockDim.x + threadIdx.x;   // 110592
    if (idx >= NF*256*OC) return;
    int o  = idx & 15;
    int ip = (idx >> 4) & 255;
    int f  = idx >> 12;

    float q = rintf(w[o*NF + f] / swp[0]);   // round-half-even like jnp.round
    q = fminf(fmaxf(q, -127.0f), 127.0f);
    int iw = (int)q + 128;

    int2 hl = ((const int2*)lut)[ip*256 + iw];   // (hi, lo)
    short v = (short)(hl.x*256 + (hl.y & 255));

    if (o < 8) g_prodA[(f*256 + ip)*8 + o]     = v;
    else       g_prodB[(f*256 + ip)*8 + (o-8)] = v;
}

// ---------------------------------------------------------------------------
// Conv: 296 blocks = 2 per SM (one per channel half), 64 warps/SM.
// Block j>>1 owns balanced global-row range [s,e) (6-7 rows); thread = pixel.
// Half-table (108KB) + tile in SMEM; 2-slot circular LDS.128 buffer (MLP=2).
// ---------------------------------------------------------------------------
#define SM_A_BYTES  (NF*256*8*2)          // 110592
#define TILE_STRIDE 1170                  // 9 rows x 130 cols (max TR = 9)
#define SM_TOTAL    (SM_A_BYTES + 3*TILE_STRIDE + 16)   // 114118 -> x2 fits 228KB/SM

__device__ __forceinline__ int tap_byte(const unsigned char* tb, int f,
                                        bool vT, bool vB)
{
    // f is compile-time after unroll: offsets fold to immediates
    int cin = f / 9, dh = (f % 9) / 3, dw = f % 3;
    int v = (int)tb[cin*TILE_STRIDE + dh*130 + dw];
    if (dh == 0) v = vT ? v : 128;    // top image boundary -> pad
    if (dh == 2) v = vB ? v : 128;    // bottom image boundary -> pad
    return v;
}

__global__ __launch_bounds__(1024, 2)
void conv_kernel(const float* __restrict__ x,
                 const float* __restrict__ bias,
                 const float* __restrict__ sxp,
                 const float* __restrict__ swp,
                 float* __restrict__ out)
{
    extern __shared__ char smem[];
    unsigned char* stile = (unsigned char*)(smem + SM_A_BYTES);

    const int tid  = threadIdx.x;
    const int half = blockIdx.x & 1;             // 0: ch0-7, 1: ch8-15
    const int j    = blockIdx.x >> 1;            // row-range id, 0..147

    // Balanced contiguous global-row range [s, e)
    const int s  = (j * NROWS_TOT) / NSPLIT;
    const int e  = ((j + 1) * NROWS_TOT) / NSPLIT;
    const int TR = e - s + 2;                    // tile rows incl. halo (8 or 9)

    // Stage this block's 108KB half-table
    {
        const int4* src = half ? (const int4*)g_prodB : (const int4*)g_prodA;
        int4* dst = (int4*)smem;
        for (int i = tid; i < SM_A_BYTES/16; i += 1024)
            dst[i] = src[i];
    }

    // Stage + quantize tile [3][TR][130]; tile row rr <-> global row s-1+rr.
    {
        const float sx = sxp[0];
        #pragma unroll 1
        for (int cin = 0; cin < 3; cin++) {
            for (int t = tid; t < TR*130; t += 1024) {
                int rr = t / 130;
                int cc = t - rr*130;
                int g  = s - 1 + rr;             // global row
                int ww = cc - 1;
                unsigned char v = 128;
                if ((unsigned)g < (unsigned)NROWS_TOT && (unsigned)ww < 128u) {
                    int b = g >> 7, h = g & 127;
                    float xf = x[((b*3 + cin)*128 + h)*128 + ww];
                    float q = rintf(xf / sx);    // round-half-even
                    q = fminf(fmaxf(q, -127.0f), 127.0f);
                    v = (unsigned char)((int)q + 128);
                }
                stile[cin*TILE_STRIDE + t] = v;
            }
        }
    }
    __syncthreads();

    const int act = (e - s) * 128;               // active pixels (768 or 896)
    if (tid >= act) return;                      // idle warps retire (no syncs below)

    const int rl = tid >> 7;                     // local row
    const int c  = tid & 127;                    // column
    const int r  = s + rl;                       // global row
    const int h  = r & 127;
    const int b  = r >> 7;
    const bool vT = (h != 0);                    // warp-uniform predicates
    const bool vB = (h != 127);
    const unsigned char* tb = &stile[rl*130 + c];
    const uint4* T = (const uint4*)smem;

    int acc[8];
    #pragma unroll
    for (int o = 0; o < 8; o++) acc[o] = 0;

    // 2-slot circular register buffer: 2 LDS.128 in flight per warp
    uint4 b0, b1;
    {
        int ip0 = tap_byte(tb, 0, vT, vB);
        int ip1 = tap_byte(tb, 1, vT, vB);
        b0 = T[0*256 + ip0];
        b1 = T[1*256 + ip1];
    }

    #pragma unroll
    for (int f = 0; f < 27; f++) {
        uint4 v = (f & 1) ? b1 : b0;
        if (f + 2 < 27) {                        // refill this slot with tap f+2
            int ipn = tap_byte(tb, f + 2, vT, vB);
            if (f & 1) b1 = T[(f + 2)*256 + ipn];
            else       b0 = T[(f + 2)*256 + ipn];
        }
        acc[0] = __dp2a_lo((int)v.x, 0x0001, acc[0]);
        acc[1] = __dp2a_lo((int)v.x, 0x0100, acc[1]);
        acc[2] = __dp2a_lo((int)v.y, 0x0001, acc[2]);
        acc[3] = __dp2a_lo((int)v.y, 0x0100, acc[3]);
        acc[4] = __dp2a_lo((int)v.z, 0x0001, acc[4]);
        acc[5] = __dp2a_lo((int)v.z, 0x0100, acc[5]);
        acc[6] = __dp2a_lo((int)v.w, 0x0001, acc[6]);
        acc[7] = __dp2a_lo((int)v.w, 0x0100, acc[7]);
        asm volatile("" ::: "memory");           // bound motion: 2-tap window
    }

    const float sc = sxp[0] * swp[0];
    float* ob = &out[((b*OC + half*8)*128 + h)*128 + c];
    #pragma unroll
    for (int o = 0; o < 8; o++)
        ob[o*128*128] = (float)acc[o] * sc + __ldg(&bias[half*8 + o]);
}

// ---------------------------------------------------------------------------
extern "C" void kernel_launch(void* const* d_in, const int* in_sizes, int n_in,
                              void* d_out, int out_size)
{
    const float* x    = (const float*)d_in[0];
    const float* w    = (const float*)d_in[1];
    const float* bias = (const float*)d_in[2];
    const float* sx   = (const float*)d_in[3];
    const float* sw   = (const float*)d_in[4];
    const int*   lut  = (const int*)d_in[5];
    float* out = (float*)d_out;

    cudaFuncSetAttribute(conv_kernel,
                         cudaFuncAttributeMaxDynamicSharedMemorySize, SM_TOTAL);

    prep_table<<<(NF*256*OC + 255) / 256, 256>>>(w, sw, lut);
    conv_kernel<<<GRID_CONV, 1024, SM_TOTAL>>>(x, bias, sx, sw, out);
}

// round 14
// speedup vs baseline: 1.0137x; 1.0137x over previous
#include <cuda_runtime.h>
#include <stdint.h>

// Problem constants
#define NB   8
#define HW   128
#define OC   16
#define NF   27
#define NROWS_TOT 1024        // NB*HW global output rows
#define GRID_CONV 148

// Device scratch: two half-tables, 16B rows (8 channels each).
__device__ __align__(16) short g_prodA[NF*256*8];   // [f][ip][o:0-7]   108KB
__device__ __align__(16) short g_prodB[NF*256*8];   // [f][ip][o:8-15]  108KB

// ---------------------------------------------------------------------------
// Table builder: one thread per (f, ip, o).
// ---------------------------------------------------------------------------
__global__ void prep_table(const float* __restrict__ w,
                           const float* __restrict__ swp,
                           const int*   __restrict__ lut)
{
    int idx = blockIdx.x * blockDim.x + threadIdx.x;   // 110592
    if (idx >= NF*256*OC) return;
    int o  = idx & 15;
    int ip = (idx >> 4) & 255;
    int f  = idx >> 12;

    float q = rintf(w[o*NF + f] / swp[0]);   // round-half-even like jnp.round
    q = fminf(fmaxf(q, -127.0f), 127.0f);
    int iw = (int)q + 128;

    int2 hl = ((const int2*)lut)[ip*256 + iw];   // (hi, lo)
    short v = (short)(hl.x*256 + (hl.y & 255));

    if (o < 8) g_prodA[(f*256 + ip)*8 + o]     = v;
    else       g_prodB[(f*256 + ip)*8 + (o-8)] = v;
}

// ---------------------------------------------------------------------------
// Conv: 148 blocks (one per SM), balanced contiguous row ranges (6-7 rows).
// Thread pair = pixel (tid&1 selects channel half). Table staged via
// cp.async in 3 cin chunks, overlapped with cin-ordered compute.
// ---------------------------------------------------------------------------
#define SM_A_BYTES   (NF*256*8*2)           // 110592 per half
#define SM_AB_BYTES  (2*SM_A_BYTES)         // 221184
#define CHUNK_I4     2304                   // int4 units per half per cin (36864B)
#define TILE_STRIDE  1170                   // 9 rows x 130 cols (max TR = 9)
#define SM_TOTAL     (SM_AB_BYTES + 3*TILE_STRIDE + 16)

#define CP_ASYNC16(dst_u32, src)                                        \
    asm volatile("cp.async.cg.shared.global [%0], [%1], 16;"            \
                 :: "r"(dst_u32), "l"(src) : "memory")

__device__ __forceinline__ void accum9(const uint4* __restrict__ T,
                                       const unsigned char* __restrict__ tb,
                                       bool vT, bool vB, int cin, int* acc)
{
    int ipx[9];
    #pragma unroll
    for (int dh = 0; dh < 3; dh++)
        #pragma unroll
        for (int dw = 0; dw < 3; dw++) {
            int v = (int)tb[cin*TILE_STRIDE + dh*130 + dw];
            if (dh == 0) v = vT ? v : 128;   // top image boundary -> pad
            if (dh == 2) v = vB ? v : 128;   // bottom image boundary -> pad
            ipx[dh*3 + dw] = v;
        }
    #pragma unroll
    for (int t = 0; t < 9; t++) {
        uint4 v = T[(cin*9 + t)*256 + ipx[t]];
        acc[0] = __dp2a_lo((int)v.x, 0x0001, acc[0]);
        acc[1] = __dp2a_lo((int)v.x, 0x0100, acc[1]);
        acc[2] = __dp2a_lo((int)v.y, 0x0001, acc[2]);
        acc[3] = __dp2a_lo((int)v.y, 0x0100, acc[3]);
        acc[4] = __dp2a_lo((int)v.z, 0x0001, acc[4]);
        acc[5] = __dp2a_lo((int)v.z, 0x0100, acc[5]);
        acc[6] = __dp2a_lo((int)v.w, 0x0001, acc[6]);
        acc[7] = __dp2a_lo((int)v.w, 0x0100, acc[7]);
    }
}

__global__ __launch_bounds__(1024, 1)
void conv_kernel(const float* __restrict__ x,
                 const float* __restrict__ bias,
                 const float* __restrict__ sxp,
                 const float* __restrict__ swp,
                 float* __restrict__ out)
{
    extern __shared__ char smem[];
    unsigned char* stile = (unsigned char*)(smem + SM_AB_BYTES);

    const int tid = threadIdx.x;
    const int bid = blockIdx.x;

    // Balanced contiguous global-row range [s, e)
    const int s  = (bid * NROWS_TOT) / GRID_CONV;
    const int e  = ((bid + 1) * NROWS_TOT) / GRID_CONV;
    const int TR = e - s + 2;                    // tile rows incl. halo

    // --- Issue table staging: 3 cp.async commit groups, one per cin chunk ---
    {
        const uint32_t smA = (uint32_t)__cvta_generic_to_shared(smem);
        const uint32_t smB = smA + SM_A_BYTES;
        const char* gA = (const char*)g_prodA;
        const char* gB = (const char*)g_prodB;
        #pragma unroll
        for (int cch = 0; cch < 3; cch++) {
            int i0 = cch*CHUNK_I4 + tid;
            CP_ASYNC16(smA + i0*16,          gA + i0*16);
            CP_ASYNC16(smB + i0*16,          gB + i0*16);
            CP_ASYNC16(smA + (i0+1024)*16,   gA + (i0+1024)*16);
            CP_ASYNC16(smB + (i0+1024)*16,   gB + (i0+1024)*16);
            if (tid < CHUNK_I4 - 2048) {     // 256 remaining
                CP_ASYNC16(smA + (i0+2048)*16, gA + (i0+2048)*16);
                CP_ASYNC16(smB + (i0+2048)*16, gB + (i0+2048)*16);
            }
            asm volatile("cp.async.commit_group;" ::: "memory");
        }
    }

    // --- Stage + quantize tile [3][TR][130] with regular loads ---
    {
        const float sx = sxp[0];
        #pragma unroll 1
        for (int cin = 0; cin < 3; cin++) {
            for (int t = tid; t < TR*130; t += 1024) {
                int rr = t / 130;
                int cc = t - rr*130;
                int g  = s - 1 + rr;             // global row
                int ww = cc - 1;
                unsigned char v = 128;
                if ((unsigned)g < (unsigned)NROWS_TOT && (unsigned)ww < 128u) {
                    int b = g >> 7, h = g & 127;
                    float xf = x[((b*3 + cin)*128 + h)*128 + ww];
                    float q = rintf(xf / sx);    // round-half-even
                    q = fminf(fmaxf(q, -127.0f), 127.0f);
                    v = (unsigned char)((int)q + 128);
                }
                stile[cin*TILE_STRIDE + t] = v;
            }
        }
    }

    // Chunk 0 (cin0 tables) + tile ready
    asm volatile("cp.async.wait_group 2;" ::: "memory");
    __syncthreads();

    const int   hf = tid & 1;                    // channel half
    const uint4* T = (const uint4*)(smem + hf*SM_A_BYTES);
    const float sc = sxp[0] * swp[0];
    const int   P  = (e - s) * 128;              // pixels (768 or 896) >= 512

    // --- Wave 0: all 1024 threads (512 pixels), cin-pipelined with staging ---
    {
        const int pp = tid >> 1;                 // < 512 <= P always
        const int rl = pp >> 7;
        const int c  = pp & 127;
        const int r  = s + rl;
        const int h  = r & 127;
        const int b  = r >> 7;
        const bool vT = (h != 0);
        const bool vB = (h != 127);
        const unsigned char* tb = &stile[rl*130 + c];

        int acc[8];
        #pragma unroll
        for (int o = 0; o < 8; o++) acc[o] = 0;

        accum9(T, tb, vT, vB, 0, acc);           // cin0 while cin1/2 stream in

        asm volatile("cp.async.wait_group 1;" ::: "memory");
        __syncthreads();
        accum9(T, tb, vT, vB, 1, acc);

        asm volatile("cp.async.wait_group 0;" ::: "memory");
        __syncthreads();
        accum9(T, tb, vT, vB, 2, acc);

        float* ob = &out[((b*OC + hf*8)*128 + h)*128 + c];
        #pragma unroll
        for (int o = 0; o < 8; o++)
            ob[o*128*128] = (float)acc[o] * sc + __ldg(&bias[hf*8 + o]);
    }

    // --- Remaining pixels: table fully resident, plain 27-tap loop ---
    #pragma unroll 1
    for (int pp = (tid >> 1) + 512; pp < P; pp += 512) {
        const int rl = pp >> 7;
        const int c  = pp & 127;
        const int r  = s + rl;
        const int h  = r & 127;
        const int b  = r >> 7;
        const bool vT = (h != 0);
        const bool vB = (h != 127);
        const unsigned char* tb = &stile[rl*130 + c];

        int acc[8];
        #pragma unroll
        for (int o = 0; o < 8; o++) acc[o] = 0;

        accum9(T, tb, vT, vB, 0, acc);
        accum9(T, tb, vT, vB, 1, acc);
        accum9(T, tb, vT, vB, 2, acc);

        float* ob = &out[((b*OC + hf*8)*128 + h)*128 + c];
        #pragma unroll
        for (int o = 0; o < 8; o++)
            ob[o*128*128] = (float)acc[o] * sc + __ldg(&bias[hf*8 + o]);
    }
}

// ---------------------------------------------------------------------------
extern "C" void kernel_launch(void* const* d_in, const int* in_sizes, int n_in,
                              void* d_out, int out_size)
{
    const float* x    = (const float*)d_in[0];
    const float* w    = (const float*)d_in[1];
    const float* bias = (const float*)d_in[2];
    const float* sx   = (const float*)d_in[3];
    const float* sw   = (const float*)d_in[4];
    const int*   lut  = (const int*)d_in[5];
    float* out = (float*)d_out;

    cudaFuncSetAttribute(conv_kernel,
                         cudaFuncAttributeMaxDynamicSharedMemorySize, SM_TOTAL);

    prep_table<<<(NF*256*OC + 255) / 256, 256>>>(w, sw, lut);
    conv_kernel<<<GRID_CONV, 1024, SM_TOTAL>>>(x, bias, sx, sw, out);
}